// round 3
// baseline (speedup 1.0000x reference)
#include <cuda_runtime.h>

#define EPS 1e-7f

constexpr int T = 32;
constexpr int S = 2048;
constexpr int B = 512;
constexpr int SW = 16;          // s per block (= warps)
constexpr int BTILE = 8;        // b staged per tile
constexpr int BGROUPS = 4;
constexpr int BPG = B / BGROUPS;    // 128
constexpr int NSB = S / SW;         // 128
constexpr int BT = B * T;           // 16384

constexpr int BSTR = 36;            // floats per b inside an s-row (32 + pad)
constexpr int XSROW = BTILE * BSTR + 4;     // 292: 16B-aligned, !=0 mod 32
constexpr int XS_FLOATS = SW * XSROW;       // 4672
constexpr int OP_FLOATS = BTILE * 32 * 17;  // 4352
constexpr int SMEM_BYTES = (XS_FLOATS + OP_FLOATS) * 4;   // 36096 B

__device__ float g_partial[(size_t)NSB * BT];   // 8 MB scratch, deterministic
__device__ float g_partial2[8 * BT];

__device__ __forceinline__ float tanh_approx(float x) {
    float y; asm("tanh.approx.f32 %0, %1;" : "=f"(y) : "f"(x)); return y;
}
__device__ __forceinline__ unsigned long long pack2(float lo, float hi) {
    unsigned long long r;
    asm("mov.b64 %0, {%1, %2};" : "=l"(r) : "f"(lo), "f"(hi));
    return r;
}
__device__ __forceinline__ void fma2(unsigned long long& d, unsigned long long a,
                                     unsigned long long b, unsigned long long c) {
    asm("fma.rn.f32x2 %0, %1, %2, %3;" : "=l"(d) : "l"(a), "l"(b), "l"(c));
}
__device__ __forceinline__ float hsum2(unsigned long long a) {
    float lo, hi;
    asm("mov.b64 {%0, %1}, %2;" : "=f"(lo), "=f"(hi) : "l"(a));
    return lo + hi;
}

__global__ __launch_bounds__(512, 1) void attn_main(
    const float* __restrict__ inp, const float* __restrict__ msk,
    const float* __restrict__ W,   const float* __restrict__ bias)
{
    extern __shared__ float sm[];
    float* xs = sm;                 // [s=16][b=8][t=32] row pitch 292
    float* op = sm + XS_FLOATS;     // [b=8][u=32][w=16 pad 17]

    const int tid  = threadIdx.x;
    const int w    = tid >> 5;          // warp id = local s
    const int lane = tid & 31;
    const int ug   = lane & 7;          // u-group: u = 4*ug + j
    const int bq   = lane >> 3;         // batch quadrant within pass
    const int s0   = blockIdx.x * SW;
    const int bb   = blockIdx.y * BPG;
    const int s    = s0 + w;

    // W register-resident: w2[j*16+k] = {W[2k][4ug+j], W[2k+1][4ug+j]} for s
    unsigned long long w2[64];
    {
        const float* Wp = W + s * (T * T) + 4 * ug;
        #pragma unroll
        for (int k = 0; k < 16; k++)
            #pragma unroll
            for (int j = 0; j < 4; j++)
                w2[j * 16 + k] = pack2(Wp[(2 * k) * 32 + j], Wp[(2 * k + 1) * 32 + j]);
    }
    float brg[4];
    #pragma unroll
    for (int j = 0; j < 4; j++) brg[j] = bias[s * 32 + 4 * ug + j];

    // staging mapping: sl = s-local (coalesced 64B across half-warp), tt = t
    const int sl = tid & 15;
    const int tt = tid >> 4;
    const float* ip0 = inp + (size_t)bb * (T * S) + (size_t)tt * S + s0 + sl;
    const float* mp0 = msk + (size_t)bb * (T * S) + (size_t)tt * S + s0 + sl;

    float vi[BTILE], vm[BTILE];
    #pragma unroll
    for (int bl = 0; bl < BTILE; bl++) {
        size_t off = (size_t)bl * (T * S);
        vi[bl] = ip0[off];
        vm[bl] = mp0[off];
    }

    for (int bt = 0; bt < BPG; bt += BTILE) {
        // ---- stage x = inp*mask -> xs[sl][bl][tt] ----
        {
            float* xrow = xs + sl * XSROW + tt;
            #pragma unroll
            for (int bl = 0; bl < BTILE; bl++)
                xrow[bl * BSTR] = vi[bl] * vm[bl];
        }
        __syncthreads();

        if (bt + BTILE < BPG) {
            const float* ipn = ip0 + (size_t)(bt + BTILE) * (T * S);
            const float* mpn = mp0 + (size_t)(bt + BTILE) * (T * S);
            #pragma unroll
            for (int bl = 0; bl < BTILE; bl++) {
                size_t off = (size_t)bl * (T * S);
                vi[bl] = ipn[off];
                vm[bl] = mpn[off];
            }
        }

        // ---- compute: 2 passes x 4 batch (lane-quadrant), 4 u per lane ----
        #pragma unroll
        for (int p = 0; p < 2; p++) {
            const int bl = p * 4 + bq;
            const float* xb = xs + w * XSROW + bl * BSTR;
            const ulonglong2* xq = (const ulonglong2*)xb;

            unsigned long long a0 = 0, a1 = 0, a2 = 0, a3 = 0;
            #pragma unroll
            for (int h = 0; h < 8; h++) {
                ulonglong2 v = xq[h];    // broadcast LDS.128: x[4h..4h+3]
                fma2(a0, v.x, w2[0 * 16 + 2 * h], a0);
                fma2(a1, v.x, w2[1 * 16 + 2 * h], a1);
                fma2(a2, v.x, w2[2 * 16 + 2 * h], a2);
                fma2(a3, v.x, w2[3 * 16 + 2 * h], a3);
                fma2(a0, v.y, w2[0 * 16 + 2 * h + 1], a0);
                fma2(a1, v.y, w2[1 * 16 + 2 * h + 1], a1);
                fma2(a2, v.y, w2[2 * 16 + 2 * h + 1], a2);
                fma2(a3, v.y, w2[3 * 16 + 2 * h + 1], a3);
            }
            float e0 = __expf(tanh_approx(hsum2(a0) + brg[0]));
            float e1 = __expf(tanh_approx(hsum2(a1) + brg[1]));
            float e2 = __expf(tanh_approx(hsum2(a2) + brg[2]));
            float e3 = __expf(tanh_approx(hsum2(a3) + brg[3]));

            float r = (e0 + e1) + (e2 + e3);
            r += __shfl_xor_sync(~0u, r, 1);
            r += __shfl_xor_sync(~0u, r, 2);
            r += __shfl_xor_sync(~0u, r, 4);   // sum over 8-lane u-group

            float4 xu = *(const float4*)(xb + 4 * ug);   // x at t = u
            float inv = __fdividef(1.f, r + EPS);

            float* od = op + (bl * 32 + 4 * ug) * 17 + w;
            od[0]      = e0 * inv * xu.x;
            od[17]     = e1 * inv * xu.y;
            od[34]     = e2 * inv * xu.z;
            od[51]     = e3 * inv * xu.w;
        }
        __syncthreads();

        // ---- reduce 16 warp contributions -> partial slice ----
        if (tid < BTILE * 32) {
            const int blr = tid >> 5;
            const float* r = op + (blr * 32 + lane) * 17;
            float sum = 0.f;
            #pragma unroll
            for (int k = 0; k < 16; k++) sum += r[k];
            g_partial[(size_t)blockIdx.x * BT + (size_t)(bb + bt + blr) * T + lane] = sum;
        }
        // next tile's post-staging __syncthreads orders op reuse
    }
}

__global__ void attn_reduceA()
{
    const int i = blockIdx.x * 256 + threadIdx.x;
    const int j = blockIdx.y;
    const float* p = g_partial + (size_t)j * 16 * BT + i;
    float s = 0.f;
    #pragma unroll
    for (int k = 0; k < 16; k++) s += p[(size_t)k * BT];
    g_partial2[j * BT + i] = s;
}

__global__ void attn_reduceB(float* __restrict__ out)
{
    const int i = blockIdx.x * 256 + threadIdx.x;
    float s = 0.f;
    #pragma unroll
    for (int j = 0; j < 8; j++) s += g_partial2[j * BT + i];
    out[i] = s;
}

extern "C" void kernel_launch(void* const* d_in, const int* in_sizes, int n_in,
                              void* d_out, int out_size)
{
    const float* inp  = (const float*)d_in[0];
    const float* msk  = (const float*)d_in[1];
    const float* W    = (const float*)d_in[2];
    const float* bias = (const float*)d_in[3];
    float* out = (float*)d_out;

    dim3 grid(NSB, BGROUPS);
    attn_main<<<grid, 512, SMEM_BYTES>>>(inp, msk, W, bias);
    attn_reduceA<<<dim3(BT / 256, 8), 256>>>();
    attn_reduceB<<<BT / 256, 256>>>(out);
}

// round 5
// speedup vs baseline: 3.2654x; 3.2654x over previous
#include <cuda_runtime.h>

#define EPS 1e-7f

constexpr int T = 32;
constexpr int S = 2048;
constexpr int B = 512;
constexpr int SW = 8;                // warps per block = s per block
constexpr int BTILE = 8;             // b staged per tile
constexpr int BGROUPS = 2;
constexpr int BPG = B / BGROUPS;     // 256
constexpr int NSB = S / SW;          // 256 s-blocks
constexpr int BT = B * T;            // 16384

constexpr int BST = 36;              // float stride per b in xs (16B-aligned, bank-spread)
constexpr int XROW = BTILE * BST + 4;    // 292 floats per s-row
constexpr int XS = SW * XROW;            // 2336 floats per buffer
constexpr int OPB = 296;                 // per-b stride in op (8 mod 32)
constexpr int OPSZ = BTILE * OPB;        // 2368 floats per buffer
// total static smem: 2*(XS+OPSZ)*4 = 37632 B  (< 48KB, no attribute needed)

__device__ float g_partial[(size_t)NSB * BT];    // 16 MB deterministic scratch
__device__ float g_partial2[16 * BT];            // 1 MB

__device__ __forceinline__ float tanh_approx(float x) {
    float y; asm("tanh.approx.f32 %0, %1;" : "=f"(y) : "f"(x)); return y;
}
__device__ __forceinline__ unsigned long long pack2(float lo, float hi) {
    unsigned long long r;
    asm("mov.b64 %0, {%1, %2};" : "=l"(r) : "f"(lo), "f"(hi));
    return r;
}
__device__ __forceinline__ void fma2(unsigned long long& d, unsigned long long a,
                                     unsigned long long b, unsigned long long c) {
    asm("fma.rn.f32x2 %0, %1, %2, %3;" : "=l"(d) : "l"(a), "l"(b), "l"(c));
}
__device__ __forceinline__ float hsum2(unsigned long long a) {
    float lo, hi;
    asm("mov.b64 {%0, %1}, %2;" : "=f"(lo), "=f"(hi) : "l"(a));
    return lo + hi;
}

__global__ __launch_bounds__(256, 1) void attn_main(
    const float* __restrict__ inp, const float* __restrict__ msk,
    const float* __restrict__ W,   const float* __restrict__ bias)
{
    __shared__ float sm[2 * XS + 2 * OPSZ];
    float* xsb[2] = { sm, sm + XS };
    float* opb[2] = { sm + 2 * XS, sm + 2 * XS + OPSZ };

    const int tid  = threadIdx.x;
    const int w    = tid >> 5;            // warp id = local s
    const int lane = tid & 31;
    const int ug   = lane & 7;            // u-group: this lane owns u = ug + 8j, j=0..3
    const int bq   = lane >> 3;           // batch slot within pass (4 per pass)
    const int s0   = blockIdx.x * SW;
    const int bb   = blockIdx.y * BPG;
    const int s    = s0 + w;

    // W register-resident: w2[j*16+k] = {W[2k][ug+8j], W[2k+1][ug+8j]} for this s.
    // 64 x f32x2 = 128 registers; 256 thr/block gives a 255-reg budget -> no spill.
    unsigned long long w2[64];
    {
        const float* Wp = W + s * (T * T) + ug;
        #pragma unroll
        for (int j = 0; j < 4; j++)
            #pragma unroll
            for (int k = 0; k < 16; k++)
                w2[j * 16 + k] = pack2(Wp[(2 * k) * 32 + 8 * j],
                                       Wp[(2 * k + 1) * 32 + 8 * j]);
    }
    float brg[4];
    #pragma unroll
    for (int j = 0; j < 4; j++) brg[j] = bias[s * 32 + ug + 8 * j];

    // staging mapping: sl = local s (8 consecutive -> 32B sectors), tt = t
    const int sl = tid & 7;
    const int tt = tid >> 3;
    const float* ip0 = inp + (size_t)bb * (T * S) + (size_t)tt * S + s0 + sl;
    const float* mp0 = msk + (size_t)bb * (T * S) + (size_t)tt * S + s0 + sl;

    float vi[BTILE], vm[BTILE];
    #pragma unroll
    for (int bl = 0; bl < BTILE; bl++) {
        size_t off = (size_t)bl * (T * S);
        vi[bl] = ip0[off];
        vm[bl] = mp0[off];
    }

    const int rbl = tid >> 5;    // reduce role: b index
    const int ru  = lane;        // reduce role: u index

    for (int bt = 0; bt < BPG; bt += BTILE) {
        const int ti  = bt / BTILE;
        const int cur = ti & 1;

        // ---- stage x = inp*mask -> xs[cur][sl][bl][tt]  (conflict-free STS) ----
        {
            float* xrow = xsb[cur] + sl * XROW + tt;
            #pragma unroll
            for (int bl = 0; bl < BTILE; bl++)
                xrow[bl * BST] = vi[bl] * vm[bl];
        }
        __syncthreads();   // xs[cur] ready; op[cur^1] (prev tile) ready

        // ---- overlapped: reduce previous tile's op -> g_partial ----
        if (ti > 0) {
            const float* r = opb[cur ^ 1] + rbl * OPB + ru * 9;
            float sum = 0.f;
            #pragma unroll
            for (int k = 0; k < SW; k++) sum += r[k];
            g_partial[(size_t)blockIdx.x * BT +
                      (size_t)(bb + bt - BTILE + rbl) * T + ru] = sum;
        }

        // ---- prefetch next tile ----
        if (bt + BTILE < BPG) {
            const float* ipn = ip0 + (size_t)(bt + BTILE) * (T * S);
            const float* mpn = mp0 + (size_t)(bt + BTILE) * (T * S);
            #pragma unroll
            for (int bl = 0; bl < BTILE; bl++) {
                size_t off = (size_t)bl * (T * S);
                vi[bl] = ipn[off];
                vm[bl] = mpn[off];
            }
        }

        // ---- compute: 2 passes x 4 b (lane quadrant), 4 u per lane ----
        #pragma unroll
        for (int p = 0; p < 2; p++) {
            const int bl = p * 4 + bq;
            const float* xb = xsb[cur] + w * XROW + bl * BST;
            const ulonglong2* xq = (const ulonglong2*)xb;

            unsigned long long a0 = 0, a1 = 0, a2 = 0, a3 = 0;
            #pragma unroll
            for (int h = 0; h < 8; h++) {
                ulonglong2 v = xq[h];   // LDS.128: x[4h..4h+3] for this lane's b
                fma2(a0, v.x, w2[0 * 16 + 2 * h], a0);
                fma2(a1, v.x, w2[1 * 16 + 2 * h], a1);
                fma2(a2, v.x, w2[2 * 16 + 2 * h], a2);
                fma2(a3, v.x, w2[3 * 16 + 2 * h], a3);
                fma2(a0, v.y, w2[0 * 16 + 2 * h + 1], a0);
                fma2(a1, v.y, w2[1 * 16 + 2 * h + 1], a1);
                fma2(a2, v.y, w2[2 * 16 + 2 * h + 1], a2);
                fma2(a3, v.y, w2[3 * 16 + 2 * h + 1], a3);
            }
            float e0 = __expf(tanh_approx(hsum2(a0) + brg[0]));
            float e1 = __expf(tanh_approx(hsum2(a1) + brg[1]));
            float e2 = __expf(tanh_approx(hsum2(a2) + brg[2]));
            float e3 = __expf(tanh_approx(hsum2(a3) + brg[3]));

            float r = (e0 + e1) + (e2 + e3);
            r += __shfl_xor_sync(~0u, r, 1);
            r += __shfl_xor_sync(~0u, r, 2);
            r += __shfl_xor_sync(~0u, r, 4);   // sum over the 8-lane u-group

            float inv = __fdividef(1.f, r + EPS);

            float xu0 = xb[ug];          // x at t = u  (~2-way LDS, minor)
            float xu1 = xb[ug + 8];
            float xu2 = xb[ug + 16];
            float xu3 = xb[ug + 24];

            float* od = opb[cur] + bl * OPB + ug * 9 + w;
            od[0]      = e0 * inv * xu0;
            od[8 * 9]  = e1 * inv * xu1;
            od[16 * 9] = e2 * inv * xu2;
            od[24 * 9] = e3 * inv * xu3;
        }
    }

    // ---- final tile's reduction ----
    __syncthreads();
    {
        const int lastcur = ((BPG / BTILE) - 1) & 1;
        const float* r = opb[lastcur] + rbl * OPB + ru * 9;
        float sum = 0.f;
        #pragma unroll
        for (int k = 0; k < SW; k++) sum += r[k];
        g_partial[(size_t)blockIdx.x * BT +
                  (size_t)(bb + BPG - BTILE + rbl) * T + ru] = sum;
    }
}

// stage A: sum 16 of 256 s-block slices (262144 threads, full-BW streaming)
__global__ void attn_reduceA()
{
    const int i = blockIdx.x * 256 + threadIdx.x;   // (b,u)
    const int j = blockIdx.y;                        // 0..15
    const float* p = g_partial + (size_t)j * 16 * BT + i;
    float s = 0.f;
    #pragma unroll
    for (int k = 0; k < 16; k++) s += p[(size_t)k * BT];
    g_partial2[j * BT + i] = s;
}

// stage B: final 16-way sum
__global__ void attn_reduceB(float* __restrict__ out)
{
    const int i = blockIdx.x * 256 + threadIdx.x;
    float s = 0.f;
    #pragma unroll
    for (int j = 0; j < 16; j++) s += g_partial2[j * BT + i];
    out[i] = s;
}

extern "C" void kernel_launch(void* const* d_in, const int* in_sizes, int n_in,
                              void* d_out, int out_size)
{
    const float* inp  = (const float*)d_in[0];
    const float* msk  = (const float*)d_in[1];
    const float* W    = (const float*)d_in[2];
    const float* bias = (const float*)d_in[3];
    float* out = (float*)d_out;

    dim3 grid(NSB, BGROUPS);
    attn_main<<<grid, 256>>>(inp, msk, W, bias);
    attn_reduceA<<<dim3(BT / 256, 16), 256>>>();
    attn_reduceB<<<BT / 256, 256>>>(out);
}